// round 5
// baseline (speedup 1.0000x reference)
#include <cuda_runtime.h>
#include <cstdint>

#define TB 320
#define BT 8
#define CH 64            // x chunk length (steps)
#define HP 68            // padded hidden stride (floats): 68*4B % 16 == 0, conflict-free

typedef unsigned long long u64;

__device__ __forceinline__ void ffma2(u64 &acc, u64 a, u64 b){
    asm("fma.rn.f32x2 %0, %1, %2, %0;" : "+l"(acc) : "l"(a), "l"(b));
}
__device__ __forceinline__ float psum(u64 a, float b){
    return __uint_as_float((unsigned)a) + __uint_as_float((unsigned)(a>>32)) + b;
}
__device__ __forceinline__ float sigf(float x){
    return __fdividef(1.0f, 1.0f + __expf(-x));
}
__device__ __forceinline__ float tanhf_fast(float x){
    return 2.0f*sigf(2.0f*x) - 1.0f;
}

__global__ __launch_bounds__(TB, 1)
void gru2_kernel(const float* __restrict__ x,
    const float* __restrict__ Wih0, const float* __restrict__ Whh0,
    const float* __restrict__ bih0, const float* __restrict__ bhh0,
    const float* __restrict__ Wih1, const float* __restrict__ Whh1,
    const float* __restrict__ bih1, const float* __restrict__ bhh1,
    const float* __restrict__ Wfc,  const float* __restrict__ bfc,
    float* __restrict__ out)
{
    __shared__ __align__(16) float xs[CH*6*BT];     // [q][e], 12 KB, chunked
    __shared__ __align__(16) float gA[192*BT];      // layer0 x-part
    __shared__ __align__(16) float gB[192*BT];      // layer0 h-part
    __shared__ __align__(16) float gC[192*BT];      // layer1 ih-part
    __shared__ __align__(16) float gD[192*BT];      // layer1 hh-part
    __shared__ __align__(16) float h1T[2][BT][HP];  // transposed h1, double buffered
    __shared__ __align__(16) float h2T[BT][HP];     // transposed h2

    const int tid = threadIdx.x;
    const int l   = tid;
    const int b0  = blockIdx.x * BT;

    for (int i=tid; i<2*BT*HP; i+=TB) ((float*)h1T)[i] = 0.f;
    for (int i=tid; i<BT*HP;   i+=TB) ((float*)h2T)[i] = 0.f;

    // ---- weight-stationary registers: TWO gate rows per lane, k-pair packed ----
    u64 w0[32], w1[32];
    float wx0[6], wx1[6];
    float bm0 = 0.f, bm1 = 0.f, bx0 = 0.f, bx1 = 0.f;

    if (l < 288){
        int r0 = 2*l;
        const float* M; int g;
        if (l < 96){
            M = Whh0; g = r0;
            bm0 = bhh0[g]; bm1 = bhh0[g+1];
            bx0 = bih0[g]; bx1 = bih0[g+1];
            #pragma unroll
            for (int i=0;i<6;i++){ wx0[i] = Wih0[g*6+i]; wx1[i] = Wih0[(g+1)*6+i]; }
        } else if (l < 192){
            M = Wih1; g = r0 - 192;
            bm0 = bih1[g]; bm1 = bih1[g+1];
        } else {
            M = Whh1; g = r0 - 384;
            bm0 = bhh1[g]; bm1 = bhh1[g+1];
        }
        const u64* Wr0 = (const u64*)(M + g*64);
        const u64* Wr1 = (const u64*)(M + (g+1)*64);
        #pragma unroll
        for (int q=0;q<32;q++){ w0[q] = Wr0[q]; w1[q] = Wr1[q]; }
    }
    __syncthreads();

    // ---- main loop: layer-0 at step t, layer-1 at step t-1 (pipelined) ----
    for (int t=0; t<=256; t++){
        const int prev = (t+1)&1;
        const int cur  = t&1;

        // refill x chunk every CH steps
        if ((t & (CH-1)) == 0 && t < 256){
            for (int idx=tid; idx<CH*6*BT; idx+=TB){
                int r = idx / (CH*6);
                int q = idx - r*(CH*6);
                xs[q*BT + r] = x[(long)(b0+r)*(256*6) + t*6 + q];
            }
            __syncthreads();
        }

        // === gate phase ===
        bool act = (l < 96) ? (t < 256) : (l < 288 && t >= 1);
        if (act){
            const float* srcb = (l < 192) ? &h1T[prev][0][0] : &h2T[0][0];
            const int lt = t & (CH-1);
            #pragma unroll
            for (int half=0; half<2; half++){
                const int c0 = half*4;
                u64 a0[4] = {0,0,0,0};
                u64 a1[4] = {0,0,0,0};
                const ulonglong2* s0 = (const ulonglong2*)(srcb + (c0+0)*HP);
                const ulonglong2* s1 = (const ulonglong2*)(srcb + (c0+1)*HP);
                const ulonglong2* s2 = (const ulonglong2*)(srcb + (c0+2)*HP);
                const ulonglong2* s3 = (const ulonglong2*)(srcb + (c0+3)*HP);
                #pragma unroll
                for (int q=0;q<16;q++){
                    ulonglong2 p0 = s0[q];
                    ffma2(a0[0], w0[2*q], p0.x); ffma2(a0[0], w0[2*q+1], p0.y);
                    ffma2(a1[0], w1[2*q], p0.x); ffma2(a1[0], w1[2*q+1], p0.y);
                    ulonglong2 p1 = s1[q];
                    ffma2(a0[1], w0[2*q], p1.x); ffma2(a0[1], w0[2*q+1], p1.y);
                    ffma2(a1[1], w1[2*q], p1.x); ffma2(a1[1], w1[2*q+1], p1.y);
                    ulonglong2 p2 = s2[q];
                    ffma2(a0[2], w0[2*q], p2.x); ffma2(a0[2], w0[2*q+1], p2.y);
                    ffma2(a1[2], w1[2*q], p2.x); ffma2(a1[2], w1[2*q+1], p2.y);
                    ulonglong2 p3 = s3[q];
                    ffma2(a0[3], w0[2*q], p3.x); ffma2(a0[3], w0[2*q+1], p3.y);
                    ffma2(a1[3], w1[2*q], p3.x); ffma2(a1[3], w1[2*q+1], p3.y);
                }
                float4 r0v = make_float4(psum(a0[0],bm0), psum(a0[1],bm0),
                                         psum(a0[2],bm0), psum(a0[3],bm0));
                float4 r1v = make_float4(psum(a1[0],bm1), psum(a1[1],bm1),
                                         psum(a1[2],bm1), psum(a1[3],bm1));
                const int r0 = 2*l;
                if (l < 96){
                    *(float4*)&gB[ r0   *BT + c0] = r0v;
                    *(float4*)&gB[(r0+1)*BT + c0] = r1v;
                    float c00=bx0,c01=bx0,c02=bx0,c03=bx0;
                    float c10=bx1,c11=bx1,c12=bx1,c13=bx1;
                    #pragma unroll
                    for (int i=0;i<6;i++){
                        float4 v = *(const float4*)&xs[(lt*6+i)*BT + c0];
                        c00 = fmaf(wx0[i], v.x, c00); c01 = fmaf(wx0[i], v.y, c01);
                        c02 = fmaf(wx0[i], v.z, c02); c03 = fmaf(wx0[i], v.w, c03);
                        c10 = fmaf(wx1[i], v.x, c10); c11 = fmaf(wx1[i], v.y, c11);
                        c12 = fmaf(wx1[i], v.z, c12); c13 = fmaf(wx1[i], v.w, c13);
                    }
                    *(float4*)&gA[ r0   *BT + c0] = make_float4(c00,c01,c02,c03);
                    *(float4*)&gA[(r0+1)*BT + c0] = make_float4(c10,c11,c12,c13);
                } else if (l < 192){
                    *(float4*)&gC[(r0-192)*BT + c0] = r0v;
                    *(float4*)&gC[(r0-191)*BT + c0] = r1v;
                } else {
                    *(float4*)&gD[(r0-384)*BT + c0] = r0v;
                    *(float4*)&gD[(r0-383)*BT + c0] = r1v;
                }
            }
        }
        __syncthreads();

        // === activation phase: 512 items (64 hidden x 8 batch), both layers ===
        for (int it = tid; it < 64*BT; it += TB){
            int j = it >> 3, e = it & 7;
            if (t < 256){
                float xr = gA[ j      *BT+e], hr = gB[ j      *BT+e];
                float xz = gA[(j+64 ) *BT+e], hz = gB[(j+64 ) *BT+e];
                float xn = gA[(j+128)*BT+e],  hn = gB[(j+128)*BT+e];
                float hold = h1T[prev][e][j];
                float r = sigf(xr+hr);
                float z = sigf(xz+hz);
                float n = tanhf_fast(fmaf(r, hn, xn));
                h1T[cur][e][j] = n + z*(hold - n);
            }
            if (t >= 1){
                float xr = gC[ j      *BT+e], hr = gD[ j      *BT+e];
                float xz = gC[(j+64 ) *BT+e], hz = gD[(j+64 ) *BT+e];
                float xn = gC[(j+128)*BT+e],  hn = gD[(j+128)*BT+e];
                float hold = h2T[e][j];
                float r = sigf(xr+hr);
                float z = sigf(xz+hz);
                float n = tanhf_fast(fmaf(r, hn, xn));
                h2T[e][j] = n + z*(hold - n);
            }
        }
        __syncthreads();
    }

    // ---- final FC ----
    if (tid < BT){
        float s = bfc[0];
        #pragma unroll
        for (int j=0;j<64;j++)
            s = fmaf(h2T[tid][j], Wfc[j], s);
        out[b0 + tid] = s;
    }
}

extern "C" void kernel_launch(void* const* d_in, const int* in_sizes, int n_in,
                              void* d_out, int out_size)
{
    (void)in_sizes; (void)n_in; (void)out_size;
    gru2_kernel<<<4096/BT, TB>>>(
        (const float*)d_in[0],
        (const float*)d_in[1], (const float*)d_in[2],
        (const float*)d_in[3], (const float*)d_in[4],
        (const float*)d_in[5], (const float*)d_in[6],
        (const float*)d_in[7], (const float*)d_in[8],
        (const float*)d_in[9], (const float*)d_in[10],
        (float*)d_out);
}

// round 7
// speedup vs baseline: 1.1426x; 1.1426x over previous
#include <cuda_runtime.h>
#include <cstdint>

#define TB 320
#define BT 4

typedef unsigned long long u64;

__device__ __forceinline__ void ffma2(u64 &acc, u64 a, u64 b){
    asm("fma.rn.f32x2 %0, %1, %2, %0;" : "+l"(acc) : "l"(a), "l"(b));
}
__device__ __forceinline__ float psum2(u64 a, u64 b, float bias){
    return (__uint_as_float((unsigned)a) + __uint_as_float((unsigned)(a>>32)))
         + (__uint_as_float((unsigned)b) + __uint_as_float((unsigned)(b>>32)))
         + bias;
}
__device__ __forceinline__ float sigf(float x){
    return __fdividef(1.0f, 1.0f + __expf(-x));
}
__device__ __forceinline__ float tanhf_fast(float x){
    return 2.0f*sigf(2.0f*x) - 1.0f;
}

__global__ __launch_bounds__(TB, 1)
void gru2_kernel(const float* __restrict__ x,
    const float* __restrict__ Wih0, const float* __restrict__ Whh0,
    const float* __restrict__ bih0, const float* __restrict__ bhh0,
    const float* __restrict__ Wih1, const float* __restrict__ Whh1,
    const float* __restrict__ bih1, const float* __restrict__ bhh1,
    const float* __restrict__ Wfc,  const float* __restrict__ bfc,
    float* __restrict__ out)
{
    __shared__ float4 x_sh[256*6];            // 24 KB  [t*6+i] over 4 batch elems
    __shared__ float4 gA[192];                // layer0 x-part
    __shared__ float4 gB[192];                // layer0 h-part
    __shared__ float4 gC[192];                // layer1 ih-part
    __shared__ float4 gD[192];                // layer1 hh-part
    __shared__ float  h1T[2][4][64];          // transposed h1, double buffered
    __shared__ float  h2T[4][64];             // transposed h2

    const int tid = threadIdx.x;
    const int l   = tid;
    const int b0  = blockIdx.x * BT;

    // ---- stage x tile ----
    {
        float* xs = (float*)x_sh;
        for (int idx = tid; idx < BT*256*6; idx += TB){
            int r = idx / (256*6);
            int q = idx - r*(256*6);
            xs[q*4 + r] = x[(long)(b0+r)*(256*6) + q];
        }
    }
    if (tid < 256){
        ((float*)h1T[1])[tid] = 0.f;
        ((float*)h2T)[tid]    = 0.f;
    }

    // ---- weight-stationary registers: TWO gate rows per lane, k-pair packed ----
    u64 w0[32], w1[32];
    float wx0[6], wx1[6];
    float bm0 = 0.f, bm1 = 0.f, bx0 = 0.f, bx1 = 0.f;

    if (l < 288){
        int r0 = 2*l;
        const float* M; int g;
        if (l < 96){
            M = Whh0; g = r0;
            bm0 = bhh0[g]; bm1 = bhh0[g+1];
            bx0 = bih0[g]; bx1 = bih0[g+1];
            #pragma unroll
            for (int i=0;i<6;i++){ wx0[i] = Wih0[g*6+i]; wx1[i] = Wih0[(g+1)*6+i]; }
        } else if (l < 192){
            M = Wih1; g = r0 - 192;
            bm0 = bih1[g]; bm1 = bih1[g+1];
        } else {
            M = Whh1; g = r0 - 384;
            bm0 = bhh1[g]; bm1 = bhh1[g+1];
        }
        const u64* Wr0 = (const u64*)(M + g*64);
        const u64* Wr1 = (const u64*)(M + (g+1)*64);
        #pragma unroll
        for (int q=0;q<32;q++){ w0[q] = Wr0[q]; w1[q] = Wr1[q]; }
    }
    __syncthreads();

    // ---- main loop: layer-0 at step t, layer-1 at step t-1 (pipelined) ----
    for (int t=0; t<=256; t++){
        const int prev = (t+1)&1;
        const int cur  = t&1;

        // === gate phase ===
        bool act = (l < 96) ? (t < 256) : (l < 288 && t >= 1);
        if (act){
            const float* src = (l < 192) ? &h1T[prev][0][0] : &h2T[0][0];
            const ulonglong2* s0 = (const ulonglong2*)(src);
            const ulonglong2* s1 = (const ulonglong2*)(src + 64);
            const ulonglong2* s2 = (const ulonglong2*)(src + 128);
            const ulonglong2* s3 = (const ulonglong2*)(src + 192);

            // 16 fully independent accumulator chains:
            // rows {0,1} x cols {0..3} x k-parity {even, odd}
            u64 e0[4] = {0,0,0,0}, o0[4] = {0,0,0,0};
            u64 e1[4] = {0,0,0,0}, o1[4] = {0,0,0,0};

            #pragma unroll
            for (int q=0;q<16;q++){
                ulonglong2 p0 = s0[q];
                ulonglong2 p1 = s1[q];
                ulonglong2 p2 = s2[q];
                ulonglong2 p3 = s3[q];
                u64 wa = w0[2*q], wb = w0[2*q+1];
                u64 wc = w1[2*q], wd = w1[2*q+1];
                ffma2(e0[0], wa, p0.x); ffma2(e0[1], wa, p1.x);
                ffma2(e0[2], wa, p2.x); ffma2(e0[3], wa, p3.x);
                ffma2(e1[0], wc, p0.x); ffma2(e1[1], wc, p1.x);
                ffma2(e1[2], wc, p2.x); ffma2(e1[3], wc, p3.x);
                ffma2(o0[0], wb, p0.y); ffma2(o0[1], wb, p1.y);
                ffma2(o0[2], wb, p2.y); ffma2(o0[3], wb, p3.y);
                ffma2(o1[0], wd, p0.y); ffma2(o1[1], wd, p1.y);
                ffma2(o1[2], wd, p2.y); ffma2(o1[3], wd, p3.y);
            }

            float4 r0v = make_float4(psum2(e0[0],o0[0],bm0), psum2(e0[1],o0[1],bm0),
                                     psum2(e0[2],o0[2],bm0), psum2(e0[3],o0[3],bm0));
            float4 r1v = make_float4(psum2(e1[0],o1[0],bm1), psum2(e1[1],o1[1],bm1),
                                     psum2(e1[2],o1[2],bm1), psum2(e1[3],o1[3],bm1));
            const int r0 = 2*l;
            if (l < 96){
                gB[r0] = r0v; gB[r0+1] = r1v;
                float c00=bx0,c01=bx0,c02=bx0,c03=bx0;
                float c10=bx1,c11=bx1,c12=bx1,c13=bx1;
                const float4* xt = &x_sh[t*6];
                #pragma unroll
                for (int i=0;i<6;i++){
                    float4 v = xt[i];
                    c00 = fmaf(wx0[i], v.x, c00); c01 = fmaf(wx0[i], v.y, c01);
                    c02 = fmaf(wx0[i], v.z, c02); c03 = fmaf(wx0[i], v.w, c03);
                    c10 = fmaf(wx1[i], v.x, c10); c11 = fmaf(wx1[i], v.y, c11);
                    c12 = fmaf(wx1[i], v.z, c12); c13 = fmaf(wx1[i], v.w, c13);
                }
                gA[r0]   = make_float4(c00,c01,c02,c03);
                gA[r0+1] = make_float4(c10,c11,c12,c13);
            } else if (l < 192){
                gC[r0-192] = r0v; gC[r0-191] = r1v;
            } else {
                gD[r0-384] = r0v; gD[r0-383] = r1v;
            }
        }
        __syncthreads();

        // === activation phase: 256 lanes, one (j, e) each, both layers ===
        if (tid < 256){
            int j = tid >> 2, e = tid & 3;
            const float* gAf = (const float*)gA;
            const float* gBf = (const float*)gB;
            const float* gCf = (const float*)gC;
            const float* gDf = (const float*)gD;
            if (t < 256){
                float xr = gAf[ j     *4+e], hr = gBf[ j     *4+e];
                float xz = gAf[(j+64) *4+e], hz = gBf[(j+64) *4+e];
                float xn = gAf[(j+128)*4+e], hn = gBf[(j+128)*4+e];
                float hold = h1T[prev][e][j];
                float r = sigf(xr+hr);
                float z = sigf(xz+hz);
                float n = tanhf_fast(fmaf(r, hn, xn));
                h1T[cur][e][j] = n + z*(hold - n);
            }
            if (t >= 1){
                float xr = gCf[ j     *4+e], hr = gDf[ j     *4+e];
                float xz = gCf[(j+64) *4+e], hz = gDf[(j+64) *4+e];
                float xn = gCf[(j+128)*4+e], hn = gDf[(j+128)*4+e];
                float hold = h2T[e][j];
                float r = sigf(xr+hr);
                float z = sigf(xz+hz);
                float n = tanhf_fast(fmaf(r, hn, xn));
                h2T[e][j] = n + z*(hold - n);
            }
        }
        __syncthreads();
    }

    // ---- final FC ----
    if (tid < BT){
        float s = bfc[0];
        #pragma unroll
        for (int j=0;j<64;j++)
            s = fmaf(h2T[tid][j], Wfc[j], s);
        out[b0 + tid] = s;
    }
}

extern "C" void kernel_launch(void* const* d_in, const int* in_sizes, int n_in,
                              void* d_out, int out_size)
{
    (void)in_sizes; (void)n_in; (void)out_size;
    gru2_kernel<<<4096/BT, TB>>>(
        (const float*)d_in[0],
        (const float*)d_in[1], (const float*)d_in[2],
        (const float*)d_in[3], (const float*)d_in[4],
        (const float*)d_in[5], (const float*)d_in[6],
        (const float*)d_in[7], (const float*)d_in[8],
        (const float*)d_in[9], (const float*)d_in[10],
        (float*)d_out);
}

// round 8
// speedup vs baseline: 1.6131x; 1.4118x over previous
#include <cuda_runtime.h>
#include <cstdint>

#define TB 384
#define BT 4

typedef unsigned long long u64;

__device__ __forceinline__ void ffma2(u64 &acc, u64 a, u64 b){
    asm("fma.rn.f32x2 %0, %1, %2, %0;" : "+l"(acc) : "l"(a), "l"(b));
}
__device__ __forceinline__ float psum(u64 a){
    return __uint_as_float((unsigned)a) + __uint_as_float((unsigned)(a>>32));
}
__device__ __forceinline__ u64 packb(float b){
    return (u64)__float_as_uint(b);      // {b, +0.0f}
}
__device__ __forceinline__ float sigf(float x){
    return __fdividef(1.0f, 1.0f + __expf(-x));
}
__device__ __forceinline__ float tanhf_fast(float x){
    return 2.0f*sigf(2.0f*x) - 1.0f;
}

__global__ __launch_bounds__(TB, 1)
void gru2_kernel(const float* __restrict__ x,
    const float* __restrict__ Wih0, const float* __restrict__ Whh0,
    const float* __restrict__ bih0, const float* __restrict__ bhh0,
    const float* __restrict__ Wih1, const float* __restrict__ Whh1,
    const float* __restrict__ bih1, const float* __restrict__ bhh1,
    const float* __restrict__ Wfc,  const float* __restrict__ bfc,
    float* __restrict__ out)
{
    __shared__ float4 x_sh[256*6];      // 24 KB : x over 4 batch cols
    __shared__ float  Wih0_sh[192*6];   // 4.5 KB
    __shared__ float  bih0n_sh[64];
    __shared__ float  P[4][64*12];      // partial sums: [0]=L0-khi [1]=ih-khi [2]=hh-klo [3]=hh-khi
    __shared__ float  h1T[2][4][64];    // h1 state, double buffered, [buf][col][k]
    __shared__ float  h2T[4][64];       // h2 state

    const int tid  = threadIdx.x;
    const int wid  = tid >> 5;
    const int lane = tid & 31;
    const int b0   = blockIdx.x * BT;

    // ---- stage x tile + W_ih0 copy ----
    {
        float* xs = (float*)x_sh;
        for (int idx = tid; idx < BT*256*6; idx += TB){
            int r = idx / (256*6);
            int q = idx - r*(256*6);
            xs[q*4 + r] = x[(long)(b0+r)*(256*6) + q];
        }
    }
    for (int i = tid; i < 192*6; i += TB) Wih0_sh[i] = Wih0[i];
    if (tid < 64) bih0n_sh[tid] = bih0[128+tid];
    for (int i = tid; i < 2*256; i += TB) ((float*)h1T)[i] = 0.f;
    for (int i = tid; i < 256;   i += TB) ((float*)h2T)[i] = 0.f;

    // ---- role decode: 12 warps ----
    // w0,1: L0 k-lo   w2,3: ih k-lo   w4,5: hh k-lo
    // w6,7: L0 k-hi   w8,9: ih k-hi   w10,11: hh k-hi
    const int khalf = (wid < 6) ? 0 : 1;
    const int role  = (wid < 6) ? (wid >> 1) : ((wid-6) >> 1);  // 0=L0, 1=ih1, 2=hh1
    const int bw    = wid & 1;
    const int j     = bw*32 + lane;                 // hidden unit 0..63
    const int r0 = j, r1 = 64+j, r2 = 128+j;        // gate rows r,z,n

    const float* M = (role==0) ? Whh0 : (role==1) ? Wih1 : Whh1;

    // weights: 3 rows x 16 u64 (k-pairs of this lane's k-half)
    u64 w[3][16];
    #pragma unroll
    for (int q=0;q<16;q++){
        w[0][q] = ((const u64*)(M + r0*64 + khalf*32))[q];
        w[1][q] = ((const u64*)(M + r1*64 + khalf*32))[q];
        w[2][q] = ((const u64*)(M + r2*64 + khalf*32))[q];
    }
    // biases (k-lo lanes carry them); n-gate h/x biases kept separate (GRU semantics)
    float b_r = 0.f, b_z = 0.f, b_n = 0.f;
    if (khalf == 0){
        if (role == 0){ b_r = bih0[r0]+bhh0[r0]; b_z = bih0[r1]+bhh0[r1]; b_n = bhh0[r2]; }
        else if (role == 1){ b_r = bih1[r0]; b_z = bih1[r1]; b_n = bih1[r2]; }
        else { b_r = bhh1[r0]; b_z = bhh1[r1]; b_n = bhh1[r2]; }
    }
    __syncthreads();

    float sr[4], sz[4], sn[4], xn4[4];   // k-lo results, live across BAR1

    for (int t=0; t<=256; t++){
        const int prev = (t+1)&1;
        const int cur  = t&1;

        // ================= Phase A : dot products =================
        bool actA = (role==0) ? (t<256) : (t>=1);
        if (actA){
            const float* src = (role==2) ? &h2T[0][0] : &h1T[prev][0][0];
            u64 acc[3][4];
            #pragma unroll
            for (int c=0;c<4;c++){
                acc[0][c] = (khalf==0) ? packb(b_r) : 0ULL;
                acc[1][c] = (khalf==0) ? packb(b_z) : 0ULL;
                acc[2][c] = (khalf==0) ? packb(b_n) : 0ULL;
            }
            const ulonglong2* s0 = (const ulonglong2*)(src +   0 + khalf*32);
            const ulonglong2* s1 = (const ulonglong2*)(src +  64 + khalf*32);
            const ulonglong2* s2 = (const ulonglong2*)(src + 128 + khalf*32);
            const ulonglong2* s3 = (const ulonglong2*)(src + 192 + khalf*32);
            #pragma unroll
            for (int q=0;q<8;q++){
                ulonglong2 p0=s0[q], p1=s1[q], p2=s2[q], p3=s3[q];
                #pragma unroll
                for (int r=0;r<3;r++){
                    u64 wa = w[r][2*q], wb = w[r][2*q+1];
                    ffma2(acc[r][0], wa, p0.x); ffma2(acc[r][1], wa, p1.x);
                    ffma2(acc[r][2], wa, p2.x); ffma2(acc[r][3], wa, p3.x);
                    ffma2(acc[r][0], wb, p0.y); ffma2(acc[r][1], wb, p1.y);
                    ffma2(acc[r][2], wb, p2.y); ffma2(acc[r][3], wb, p3.y);
                }
            }
            if (khalf == 0){
                #pragma unroll
                for (int c=0;c<4;c++){
                    sr[c]=psum(acc[0][c]); sz[c]=psum(acc[1][c]); sn[c]=psum(acc[2][c]);
                }
                if (role == 0){
                    // x-part: r,z fold into sr/sz; n-gate x-part kept separate (xn4)
                    float bn = bih0n_sh[j];
                    #pragma unroll
                    for (int c=0;c<4;c++) xn4[c] = bn;
                    const float4* xt = &x_sh[t*6];
                    #pragma unroll
                    for (int i=0;i<6;i++){
                        float4 v = xt[i];
                        float wr = Wih0_sh[r0*6+i];
                        float wz = Wih0_sh[r1*6+i];
                        float wn = Wih0_sh[r2*6+i];
                        sr[0]=fmaf(wr,v.x,sr[0]); sr[1]=fmaf(wr,v.y,sr[1]);
                        sr[2]=fmaf(wr,v.z,sr[2]); sr[3]=fmaf(wr,v.w,sr[3]);
                        sz[0]=fmaf(wz,v.x,sz[0]); sz[1]=fmaf(wz,v.y,sz[1]);
                        sz[2]=fmaf(wz,v.z,sz[2]); sz[3]=fmaf(wz,v.w,sz[3]);
                        xn4[0]=fmaf(wn,v.x,xn4[0]); xn4[1]=fmaf(wn,v.y,xn4[1]);
                        xn4[2]=fmaf(wn,v.z,xn4[2]); xn4[3]=fmaf(wn,v.w,xn4[3]);
                    }
                } else if (role == 2){
                    float* p = &P[2][j*12];           // hh-klo publishes
                    ((float4*)p)[0] = make_float4(sr[0],sr[1],sr[2],sr[3]);
                    ((float4*)p)[1] = make_float4(sz[0],sz[1],sz[2],sz[3]);
                    ((float4*)p)[2] = make_float4(sn[0],sn[1],sn[2],sn[3]);
                }
            } else {
                float* p = &P[(role==2)?3:role][j*12]; // khi partials
                ((float4*)p)[0] = make_float4(psum(acc[0][0]),psum(acc[0][1]),psum(acc[0][2]),psum(acc[0][3]));
                ((float4*)p)[1] = make_float4(psum(acc[1][0]),psum(acc[1][1]),psum(acc[1][2]),psum(acc[1][3]));
                ((float4*)p)[2] = make_float4(psum(acc[2][0]),psum(acc[2][1]),psum(acc[2][2]),psum(acc[2][3]));
            }
        }
        __syncthreads();   // BAR1

        // ================= Phase B : activations =================
        if (wid < 2){
            if (t < 256){
                const float* pH = &P[0][j*12];
                float4 a0 = ((const float4*)pH)[0];
                float4 a1 = ((const float4*)pH)[1];
                float4 a2 = ((const float4*)pH)[2];
                const float* h0 = &a0.x; const float* h1v = &a1.x; const float* h2v = &a2.x;
                #pragma unroll
                for (int c=0;c<4;c++){
                    float r  = sigf(sr[c] + h0[c]);
                    float z  = sigf(sz[c] + h1v[c]);
                    float hn = sn[c] + h2v[c];
                    float n  = tanhf_fast(fmaf(r, hn, xn4[c]));
                    float hold = h1T[prev][c][j];
                    h1T[cur][c][j] = n + z*(hold - n);
                }
            }
        } else if (wid < 4){
            if (t >= 1){
                const float* pI = &P[1][j*12];
                const float* pL = &P[2][j*12];
                const float* pH = &P[3][j*12];
                float4 i0=((const float4*)pI)[0], i1=((const float4*)pI)[1], i2=((const float4*)pI)[2];
                float4 l0=((const float4*)pL)[0], l1=((const float4*)pL)[1], l2=((const float4*)pL)[2];
                float4 k0=((const float4*)pH)[0], k1=((const float4*)pH)[1], k2=((const float4*)pH)[2];
                const float *fi0=&i0.x,*fi1=&i1.x,*fi2=&i2.x;
                const float *fl0=&l0.x,*fl1=&l1.x,*fl2=&l2.x;
                const float *fk0=&k0.x,*fk1=&k1.x,*fk2=&k2.x;
                #pragma unroll
                for (int c=0;c<4;c++){
                    float xr = sr[c] + fi0[c];
                    float xz = sz[c] + fi1[c];
                    float xn = sn[c] + fi2[c];
                    float hr = fl0[c] + fk0[c];
                    float hz = fl1[c] + fk1[c];
                    float hn = fl2[c] + fk2[c];
                    float r  = sigf(xr + hr);
                    float z  = sigf(xz + hz);
                    float n  = tanhf_fast(fmaf(r, hn, xn));
                    float hold = h2T[c][j];
                    h2T[c][j] = n + z*(hold - n);
                }
            }
        }
        __syncthreads();   // BAR2
    }

    // ---- final FC ----
    if (tid < BT){
        float s = bfc[0];
        #pragma unroll
        for (int k=0;k<64;k++)
            s = fmaf(h2T[tid][k], Wfc[k], s);
        out[b0 + tid] = s;
    }
}

extern "C" void kernel_launch(void* const* d_in, const int* in_sizes, int n_in,
                              void* d_out, int out_size)
{
    (void)in_sizes; (void)n_in; (void)out_size;
    gru2_kernel<<<4096/BT, TB>>>(
        (const float*)d_in[0],
        (const float*)d_in[1], (const float*)d_in[2],
        (const float*)d_in[3], (const float*)d_in[4],
        (const float*)d_in[5], (const float*)d_in[6],
        (const float*)d_in[7], (const float*)d_in[8],
        (const float*)d_in[9], (const float*)d_in[10],
        (float*)d_out);
}